// round 10
// baseline (speedup 1.0000x reference)
#include <cuda_runtime.h>
#include <math.h>
#include <cstdint>

// =====================================================================
// FrFTPool: out = |A · X · B^T| per 128x128 image; A,B (64x128 complex)
// built on-device from the Candan/Ozaktas FrFT closed form with the
// center crop folded in. GEMMs use packed fma.rn.f32x2 (FFMA2).
// Prep: tables fused into build_matrix (double mod-2pi + fp32 sincos).
// =====================================================================

#define NBIG 128
#define NSMALL 64
#define NIMG 256          // 8*32
#define XS_ROW 132        // padded row for transposed X in smem (floats)
#define TS_ROW 66         // padded row for T in smem (float2)
#define KCHUNK 32         // k/p tile depth for Tile staging

typedef unsigned long long u64v;

__device__ __forceinline__ u64v pk2(float lo, float hi) {
    u64v r; asm("mov.b64 %0, {%1, %2};" : "=l"(r) : "f"(lo), "f"(hi)); return r;
}
__device__ __forceinline__ void upk2(float& lo, float& hi, u64v v) {
    asm("mov.b64 {%0, %1}, %2;" : "=f"(lo), "=f"(hi) : "l"(v));
}
__device__ __forceinline__ void ffma2(u64v& d, u64v a, u64v b) {
    asm("fma.rn.f32x2 %0, %1, %2, %0;" : "+l"(d) : "l"(a), "l"(b));
}

// angle = th (double) reduced mod 2pi, then fp32 sincos: keeps double
// phase accuracy at fp32 sincos cost.
__device__ __forceinline__ float2 sincos_red(double th) {
    const double TWO_PI = 6.283185307179586476925286766559;
    double q = trunc(th * (1.0 / TWO_PI));
    float a = (float)(th - q * TWO_PI);
    float s, c;
    sincosf(a, &s, &c);
    return make_float2(c, s);
}

// ---------------- device scratch (no allocations allowed) -------------
__device__ __align__(16) float2 d_M1[NBIG * NBIG];
__device__ __align__(16) float2 d_M2[NBIG * NBIG];
__device__ __align__(16) float2 d_M3[NSMALL * NSMALL];
__device__ __align__(16) float2 d_M4[NSMALL * NSMALL];
__device__ __align__(16) float2 d_At[NBIG * NSMALL];   // At[h][i] = A[i][h]
__device__ __align__(16) float2 d_Bt[NBIG * NSMALL];   // Bt[k][j] = B[j][k]

// ---------------- 1) FrFT matrices, tables built in-block -------------
// matrix m: 0 -> order1 @N=128, 1 -> order2 @N=128,
//           2 -> -order1 @N=64,  3 -> -order2 @N=64
// M[j,k] = pref*C[2j]*( K[2(j-kk)]*C[2kk] + sum_t KC[t]*W[|t-kk|] )
//   kk = flip ? N-1-k : k,  KC[t] = K[2j-2t-1]*C[2t+1],
//   W[i] = ((i&1)?-2:2)/(pi*(2i+1))
__global__ void build_matrix_fused(const float* __restrict__ order1,
                                   const float* __restrict__ order2) {
    int m = blockIdx.y;
    int N = (m < 2) ? NBIG : NSMALL;
    int j = blockIdx.x;
    if (j >= N) return;

    float ap = ((m == 0) || (m == 2)) ? order1[0] : order2[0];
    if (m >= 2) ap = -ap;
    double a = fmod((double)ap, 4.0);
    if (a < 0.0) a += 4.0;
    int flip = 0;
    if (a > 2.0) { flip = 1; a -= 2.0; }

    double alpha = a * M_PI * 0.5;
    double tana2 = tan(alpha * 0.5);
    double sina  = sin(alpha);
    double c     = M_PI / (4.0 * (double)N * sina);
    double kch   = (M_PI / (double)N) * tana2 * 0.25;

    __shared__ float2 Ks[4 * NBIG];    // 4N-3 <= 509
    __shared__ float2 Cs[2 * NBIG];    // 2N-1 <= 255
    __shared__ float  W[NBIG];
    __shared__ float2 KC[NBIG];

    int tid = threadIdx.x;
    for (int i = tid; i < 4 * N - 3; i += 128) {
        double mm = (double)(i - (2 * N - 2));
        Ks[i] = sincos_red(c * mm * mm);
    }
    for (int p = tid; p < 2 * N - 1; p += 128) {
        double n = (double)(p - (N - 1));
        Cs[p] = sincos_red(-kch * n * n);
    }
    if (tid < N)
        W[tid] = ((tid & 1) ? -2.0f : 2.0f) / ((float)M_PI * (float)(2 * tid + 1));
    __syncthreads();

    int off = 2 * N - 2;
    if (tid < N - 1) {
        float2 K = Ks[2 * j - 2 * tid - 1 + off];
        float2 C = Cs[2 * tid + 1];
        KC[tid] = make_float2(K.x * C.x - K.y * C.y, K.x * C.y + K.y * C.x);
    }
    __syncthreads();

    int k = tid;
    if (k >= N) return;
    int kk = flip ? (N - 1 - k) : k;

    float2 Ke = Ks[2 * (j - kk) + off];
    float2 Ce = Cs[2 * kk];
    float sr = Ke.x * Ce.x - Ke.y * Ce.y;
    float si = Ke.x * Ce.y + Ke.y * Ce.x;

    #pragma unroll 4
    for (int t = 0; t < N - 1; t++) {
        int u = t - kk;
        int idx = u ^ (u >> 31);
        float sv = W[idx];
        float2 kc = KC[t];
        sr = fmaf(kc.x, sv, sr);
        si = fmaf(kc.y, sv, si);
    }

    float2 prv = sincos_red(-(1.0 - a) * M_PI * 0.25);
    float sc = (float)sqrt(c / M_PI);
    float prx = prv.x * sc, pry = prv.y * sc;
    float2 Cj = Cs[2 * j];
    float pcr = prx * Cj.x - pry * Cj.y;
    float pci = prx * Cj.y + pry * Cj.x;
    float2 outv;
    outv.x = pcr * sr - pci * si;
    outv.y = pcr * si + pci * sr;

    float2* M = (m == 0) ? d_M1 : (m == 1) ? d_M2 : (m == 2) ? d_M3 : d_M4;
    M[j * N + k] = outv;
}

// ---------------- 2) fold crop into combined matrices -----------------
// A[i,h] = sum_p M4[i,p] * M2[32+p, h]   -> stored transposed At[h][i]
// B[j,k] = sum_q M3[j,q] * M1[32+q, k]   -> stored transposed Bt[k][j]
__global__ void combine() {
    int i = blockIdx.x;          // 0..63
    int h = threadIdx.x;         // 0..127
    const float2* L = blockIdx.y ? d_M3 : d_M4;   // 64x64
    const float2* R = blockIdx.y ? d_M1 : d_M2;   // 128x128
    float ar = 0.f, ai = 0.f;
    #pragma unroll 4
    for (int p = 0; p < NSMALL; p++) {
        float2 l = L[i * NSMALL + p];
        float2 r = R[(32 + p) * NBIG + h];
        ar += l.x * r.x - l.y * r.y;
        ai += l.x * r.y + l.y * r.x;
    }
    float2* T = blockIdx.y ? d_Bt : d_At;
    T[h * NSMALL + i] = make_float2(ar, ai);
}

// ---------------- 3) main fused kernel (round-6 exact) ----------------
// block = 256 threads, one image per block.
// GEMM1: T[p,j] = sum_k X[p,k]*B[j,k]   (X real)   p<128, j<64
// GEMM2: O[i,j] = | sum_p A[i,p]*T[p,j] |          i<64,  j<64
#define SMEM_BYTES (NBIG * XS_ROW * 4 + KCHUNK * NSMALL * 8)  // 67584 + 16384

__global__ __launch_bounds__(256, 2)
void frft_pool_main(const float* __restrict__ x, float* __restrict__ out) {
    extern __shared__ float smem[];
    float*  Xs   = smem;                                // [128][132] floats
    float2* Tile = (float2*)(smem + NBIG * XS_ROW);     // [KCHUNK][64] float2

    int tid = threadIdx.x;
    int l = tid & 31;        // lane
    int w = tid >> 5;        // warp 0..7
    int img = blockIdx.x;

    // --- load X transposed into smem: Xs[k][p] = X[p][k] ---
    const float4* xg4 = (const float4*)(x + (size_t)img * (NBIG * NBIG));
    #pragma unroll
    for (int i = 0; i < 16; i++) {
        int idx4 = tid + i * 256;
        float4 v = xg4[idx4];
        int r = idx4 >> 5;            // row p
        int c = (idx4 & 31) << 2;     // col k base
        Xs[(c + 0) * XS_ROW + r] = v.x;
        Xs[(c + 1) * XS_ROW + r] = v.y;
        Xs[(c + 2) * XS_ROW + r] = v.z;
        Xs[(c + 3) * XS_ROW + r] = v.w;
    }

    // ---- GEMM1: thread computes T[4l..4l+3][8w..8w+7], packed (re,im) ----
    u64v acc[4][8];
    #pragma unroll
    for (int pp = 0; pp < 4; pp++)
        #pragma unroll
        for (int jj = 0; jj < 8; jj++) acc[pp][jj] = 0ull;

    for (int k0 = 0; k0 < NBIG; k0 += KCHUNK) {
        __syncthreads();
        {
            const ulonglong2* g = (const ulonglong2*)(d_Bt + (size_t)k0 * NSMALL);
            ulonglong2* t = (ulonglong2*)Tile;
            #pragma unroll
            for (int i = 0; i < (KCHUNK * NSMALL) / (2 * 256); i++)
                t[tid + i * 256] = g[tid + i * 256];
        }
        __syncthreads();
        #pragma unroll
        for (int kt = 0; kt < KCHUNK; kt++) {
            int k = k0 + kt;
            float4 xv = *(const float4*)&Xs[k * XS_ROW + 4 * l];
            const ulonglong2* bp = (const ulonglong2*)&Tile[kt * NSMALL + 8 * w];
            ulonglong2 b0 = bp[0], b1 = bp[1], b2 = bp[2], b3 = bp[3];
            u64v bb[8] = {b0.x, b0.y, b1.x, b1.y, b2.x, b2.y, b3.x, b3.y};
            float xsv[4] = {xv.x, xv.y, xv.z, xv.w};
            #pragma unroll
            for (int pp = 0; pp < 4; pp++) {
                u64v xs2 = pk2(xsv[pp], xsv[pp]);
                #pragma unroll
                for (int jj = 0; jj < 8; jj++) ffma2(acc[pp][jj], xs2, bb[jj]);
            }
        }
    }

    // --- write T into smem (reusing Xs region): Ts[p][j], row pitch 66 ---
    __syncthreads();
    float2* Ts = (float2*)smem;
    #pragma unroll
    for (int pp = 0; pp < 4; pp++)
        #pragma unroll
        for (int jp = 0; jp < 4; jp++)
            *(ulonglong2*)&Ts[(4 * l + pp) * TS_ROW + 8 * w + 2 * jp] =
                make_ulonglong2(acc[pp][2 * jp], acc[pp][2 * jp + 1]);

    // ---- GEMM2: thread computes O[{l,l+32}][8w..8w+7] ----
    u64v accA[2][8], accB[2][8];
    #pragma unroll
    for (int ii = 0; ii < 2; ii++)
        #pragma unroll
        for (int jj = 0; jj < 8; jj++) { accA[ii][jj] = 0ull; accB[ii][jj] = 0ull; }

    for (int p0 = 0; p0 < NBIG; p0 += KCHUNK) {
        __syncthreads();
        {
            const ulonglong2* g = (const ulonglong2*)(d_At + (size_t)p0 * NSMALL);
            ulonglong2* t = (ulonglong2*)Tile;
            #pragma unroll
            for (int i = 0; i < (KCHUNK * NSMALL) / (2 * 256); i++)
                t[tid + i * 256] = g[tid + i * 256];
        }
        __syncthreads();
        #pragma unroll
        for (int pt = 0; pt < KCHUNK; pt++) {
            int p = p0 + pt;
            float2 a0 = Tile[pt * NSMALL + l];
            float2 a1 = Tile[pt * NSMALL + l + 32];
            const ulonglong2* tp = (const ulonglong2*)&Ts[p * TS_ROW + 8 * w];
            ulonglong2 t0 = tp[0], t1 = tp[1], t2 = tp[2], t3 = tp[3];
            u64v tt[8] = {t0.x, t0.y, t1.x, t1.y, t2.x, t2.y, t3.x, t3.y};
            u64v ax0 = pk2(a0.x, a0.x), ay0 = pk2(a0.y, a0.y);
            u64v ax1 = pk2(a1.x, a1.x), ay1 = pk2(a1.y, a1.y);
            #pragma unroll
            for (int jj = 0; jj < 8; jj++) {
                ffma2(accA[0][jj], ax0, tt[jj]);
                ffma2(accB[0][jj], ay0, tt[jj]);
                ffma2(accA[1][jj], ax1, tt[jj]);
                ffma2(accB[1][jj], ay1, tt[jj]);
            }
        }
    }

    float* og = out + (size_t)img * (NSMALL * NSMALL);
    #pragma unroll
    for (int ii = 0; ii < 2; ii++) {
        int i = l + 32 * ii;
        float res[8];
        #pragma unroll
        for (int jj = 0; jj < 8; jj++) {
            float Ar, Ai, Br, Bi;
            upk2(Ar, Ai, accA[ii][jj]);
            upk2(Br, Bi, accB[ii][jj]);
            float orr = Ar - Bi;
            float oii = Ai + Br;
            res[jj] = sqrtf(orr * orr + oii * oii);
        }
        *(float4*)&og[i * NSMALL + 8 * w]     = make_float4(res[0], res[1], res[2], res[3]);
        *(float4*)&og[i * NSMALL + 8 * w + 4] = make_float4(res[4], res[5], res[6], res[7]);
    }
}

// ---------------------------------------------------------------------
extern "C" void kernel_launch(void* const* d_in, const int* in_sizes, int n_in,
                              void* d_out, int out_size) {
    const float* x  = (const float*)d_in[0];
    const float* o1 = (const float*)d_in[1];
    const float* o2 = (const float*)d_in[2];
    float* out = (float*)d_out;

    build_matrix_fused<<<dim3(NBIG, 4), 128>>>(o1, o2);
    combine<<<dim3(NSMALL, 2), 128>>>();

    cudaFuncSetAttribute(frft_pool_main,
                         cudaFuncAttributeMaxDynamicSharedMemorySize, SMEM_BYTES);
    frft_pool_main<<<NIMG, 256, SMEM_BYTES>>>(x, out);
}

// round 11
// speedup vs baseline: 1.5454x; 1.5454x over previous
#include <cuda_runtime.h>
#include <math.h>
#include <cstdint>

// =====================================================================
// FrFTPool with centrosymmetric even/odd decomposition:
//   A[63-i][127-p] = A[i][p], B[63-j][127-k] = B[j][k]  (exact)
//   GEMM1: Te[p,jh] = sum_{k<64} Xe[p,k]·BE[jh,k], To with Xo,BO
//   GEMM2: Oe[i,j] = sum_{p<64} ASE[i,p]·Tpe[p,j], Oo with ASO,Tpo
// Halves both GEMMs' flops. FFMA2 throughout, 3 block barriers.
// =====================================================================

#define NBIG 128
#define NSMALL 64
#define NIMG 256
#define XE_ROW 132        // floats, pitch of Xe/Xo rows (128 used)
#define TS_ROW 66         // float2 pitch of Tpe/Tpo rows (64 used)

typedef unsigned long long u64v;

__device__ __forceinline__ u64v pk2(float lo, float hi) {
    u64v r; asm("mov.b64 %0, {%1, %2};" : "=l"(r) : "f"(lo), "f"(hi)); return r;
}
__device__ __forceinline__ void upk2(float& lo, float& hi, u64v v) {
    asm("mov.b64 {%0, %1}, %2;" : "=f"(lo), "=f"(hi) : "l"(v));
}
__device__ __forceinline__ void ffma2(u64v& d, u64v a, u64v b) {
    asm("fma.rn.f32x2 %0, %1, %2, %0;" : "+l"(d) : "l"(a), "l"(b));
}

// ---------------- device scratch --------------------------------------
__device__ __align__(16) float2 d_M1[NBIG * NBIG];
__device__ __align__(16) float2 d_M2[NBIG * NBIG];
__device__ __align__(16) float2 d_M3[NSMALL * NSMALL];
__device__ __align__(16) float2 d_M4[NSMALL * NSMALL];
// folded operand matrices, stored transposed for staging:
__device__ __align__(16) float2 d_BE[64 * 32];    // [k<64][jh<32] = 0.5(B[jh,k]+B[63-jh,k])
__device__ __align__(16) float2 d_BO[64 * 32];    // [k][jh]      = 0.5(B[jh,k]-B[63-jh,k])
__device__ __align__(16) float2 d_ASE[64 * 32];   // [p<64][i<32] = 0.5(A[i,p]+A[i,127-p])
__device__ __align__(16) float2 d_ASO[64 * 32];   // [p][i]       = 0.5(A[i,p]-A[i,127-p])

__device__ __align__(16) float2 d_Ktab[4][4 * NBIG];
__device__ __align__(16) float2 d_Ctab[4][2 * NBIG];
__device__ float2 d_pref[4];
__device__ int    d_flip[4];

// ---------------- 1) chirp tables (DP sincos, sliced over 32 blocks) --
__global__ void build_tables(const float* __restrict__ order1,
                             const float* __restrict__ order2) {
    int m = blockIdx.x;
    int s = blockIdx.y;
    int N = (m < 2) ? NBIG : NSMALL;
    float ap = ((m == 0) || (m == 2)) ? order1[0] : order2[0];
    if (m >= 2) ap = -ap;

    double a = fmod((double)ap, 4.0);
    if (a < 0.0) a += 4.0;
    int flip = 0;
    if (a > 2.0) { flip = 1; a -= 2.0; }

    double alpha = a * M_PI * 0.5;
    double tana2 = tan(alpha * 0.5);
    double sina  = sin(alpha);
    double c     = M_PI / (4.0 * (double)N * sina);
    double kch   = (M_PI / (double)N) * tana2 * 0.25;

    int t = threadIdx.x;
    int nK = 4 * N - 3;
    int nC = 2 * N - 1;
    int i = s * 128 + t;
    if (i < nK) {
        double mm = (double)(i - (2 * N - 2));
        double sn, co; sincos(c * mm * mm, &sn, &co);
        d_Ktab[m][i] = make_float2((float)co, (float)sn);
    }
    if (t < 32) {
        int p = s * 32 + t;
        if (p < nC) {
            double n = (double)(p - (N - 1));
            double sn, co; sincos(-kch * n * n, &sn, &co);
            d_Ctab[m][p] = make_float2((float)co, (float)sn);
        }
    }
    if (s == 0 && t == 0) {
        double ph = -(1.0 - a) * M_PI * 0.25;
        double sn, co; sincos(ph, &sn, &co);
        double sc = sqrt(c / M_PI);
        d_pref[m] = make_float2((float)(co * sc), (float)(sn * sc));
        d_flip[m] = flip;
    }
}

// ---------------- 2) FrFT matrices from tables (fp32 only) ------------
__global__ void build_matrix() {
    int m = blockIdx.y;
    int N = (m < 2) ? NBIG : NSMALL;
    int j = blockIdx.x;
    if (j >= N) return;

    __shared__ float2 Ks[4 * NBIG];
    __shared__ float2 Cs[2 * NBIG];
    __shared__ float  W[NBIG];
    __shared__ float2 KC[NBIG];

    int tid = threadIdx.x;
    for (int i = tid; i < 4 * N - 3; i += 128) Ks[i] = d_Ktab[m][i];
    for (int p = tid; p < 2 * N - 1; p += 128) Cs[p] = d_Ctab[m][p];
    if (tid < N)
        W[tid] = ((tid & 1) ? -2.0f : 2.0f) / ((float)M_PI * (float)(2 * tid + 1));
    __syncthreads();

    int off = 2 * N - 2;
    if (tid < N - 1) {
        float2 K = Ks[2 * j - 2 * tid - 1 + off];
        float2 C = Cs[2 * tid + 1];
        KC[tid] = make_float2(K.x * C.x - K.y * C.y, K.x * C.y + K.y * C.x);
    }
    __syncthreads();

    int k = tid;
    if (k >= N) return;
    int flip = d_flip[m];
    int kk = flip ? (N - 1 - k) : k;

    float2 Ke = Ks[2 * (j - kk) + off];
    float2 Ce = Cs[2 * kk];
    float sr = Ke.x * Ce.x - Ke.y * Ce.y;
    float si = Ke.x * Ce.y + Ke.y * Ce.x;

    #pragma unroll 4
    for (int t = 0; t < N - 1; t++) {
        int u = t - kk;
        int idx = u ^ (u >> 31);
        float sv = W[idx];
        float2 kc = KC[t];
        sr = fmaf(kc.x, sv, sr);
        si = fmaf(kc.y, sv, si);
    }

    float2 pr = d_pref[m];
    float2 Cj = Cs[2 * j];
    float pcr = pr.x * Cj.x - pr.y * Cj.y;
    float pci = pr.x * Cj.y + pr.y * Cj.x;
    float2 outv;
    outv.x = pcr * sr - pci * si;
    outv.y = pcr * si + pci * sr;

    float2* M = (m == 0) ? d_M1 : (m == 1) ? d_M2 : (m == 2) ? d_M3 : d_M4;
    M[j * N + k] = outv;
}

// ---------------- 3) combine + fold -----------------------------------
// y=1 (B): block jb<32; thread h: which=h>>6 picks row jb or 63-jb,
//   col k=h&63; B[row,k] = sum_q M3[row,q]·M1[32+q,k]; fold to BE/BO.
// y=0 (A): block i<32; thread h<128: A[i,h] = sum_p M4[i,p]·M2[32+p,h];
//   fold in p to ASE/ASO.
__global__ void combine() {
    int jb = blockIdx.x;         // 0..31
    int h = threadIdx.x;         // 0..127
    __shared__ float2 sbuf[128];

    if (blockIdx.y) {            // ---- B side ----
        int k = h & 63;
        int row = (h >> 6) ? (63 - jb) : jb;
        float ar = 0.f, ai = 0.f;
        #pragma unroll 4
        for (int q = 0; q < NSMALL; q++) {
            float2 l2 = d_M3[row * NSMALL + q];
            float2 r2 = d_M1[(32 + q) * NBIG + k];
            ar += l2.x * r2.x - l2.y * r2.y;
            ai += l2.x * r2.y + l2.y * r2.x;
        }
        sbuf[h] = make_float2(ar, ai);
        __syncthreads();
        if (h < 64) {
            float2 a = sbuf[h], b = sbuf[h + 64];
            d_BE[h * 32 + jb] = make_float2(0.5f * (a.x + b.x), 0.5f * (a.y + b.y));
        } else {
            int k2 = h - 64;
            float2 a = sbuf[k2], b = sbuf[h];
            d_BO[k2 * 32 + jb] = make_float2(0.5f * (a.x - b.x), 0.5f * (a.y - b.y));
        }
    } else {                     // ---- A side ----
        float ar = 0.f, ai = 0.f;
        #pragma unroll 4
        for (int p = 0; p < NSMALL; p++) {
            float2 l2 = d_M4[jb * NSMALL + p];
            float2 r2 = d_M2[(32 + p) * NBIG + h];
            ar += l2.x * r2.x - l2.y * r2.y;
            ai += l2.x * r2.y + l2.y * r2.x;
        }
        sbuf[h] = make_float2(ar, ai);
        __syncthreads();
        if (h < 64) {
            float2 a = sbuf[h], b = sbuf[127 - h];
            d_ASE[h * 32 + jb] = make_float2(0.5f * (a.x + b.x), 0.5f * (a.y + b.y));
        } else {
            int p = h - 64;
            float2 a = sbuf[p], b = sbuf[127 - p];
            d_ASO[p * 32 + jb] = make_float2(0.5f * (a.x - b.x), 0.5f * (a.y - b.y));
        }
    }
}

// ---------------- 4) main fused kernel --------------------------------
// smem: Xe[64][132]f @0, Xo @33792B, tiles 32KB @67584B.
// After GEMM1, Xe/Xo region becomes Tpe[64][66]f2 / Tpo.
#define SMEM_BYTES (2 * 64 * XE_ROW * 4 + 2 * 64 * 32 * 8)   // 67584 + 32768

__global__ __launch_bounds__(256, 2)
void frft_pool_main(const float* __restrict__ x, float* __restrict__ out) {
    extern __shared__ float smem[];
    float*  Xe   = smem;                          // [64][132]
    float*  Xo   = smem + 64 * XE_ROW;            // [64][132]
    float2* Tile = (float2*)(smem + 2 * 64 * XE_ROW);  // 4096 float2

    int tid = threadIdx.x;
    int l = tid & 31;
    int w = tid >> 5;
    int img = blockIdx.x;

    // ---- load X, fold even/odd: Xe[k][p] = X[p,k]+X[p,127-k] ----
    const float4* xg4 = (const float4*)(x + (size_t)img * (NBIG * NBIG));
    #pragma unroll
    for (int it = 0; it < 8; it++) {
        int idx = tid + it * 256;        // 2048 tasks: p<128 x quad<16
        int p = idx >> 4;
        int q = idx & 15;                // k quad (k = 4q..4q+3 < 64)
        float4 v1 = xg4[p * 32 + q];
        float4 v2 = xg4[p * 32 + 31 - q];
        Xe[(4 * q + 0) * XE_ROW + p] = v1.x + v2.w;
        Xe[(4 * q + 1) * XE_ROW + p] = v1.y + v2.z;
        Xe[(4 * q + 2) * XE_ROW + p] = v1.z + v2.y;
        Xe[(4 * q + 3) * XE_ROW + p] = v1.w + v2.x;
        Xo[(4 * q + 0) * XE_ROW + p] = v1.x - v2.w;
        Xo[(4 * q + 1) * XE_ROW + p] = v1.y - v2.z;
        Xo[(4 * q + 2) * XE_ROW + p] = v1.z - v2.y;
        Xo[(4 * q + 3) * XE_ROW + p] = v1.w - v2.x;
    }
    // ---- stage BE+BO tiles (32KB) ----
    {
        const ulonglong2* g = (const ulonglong2*)d_BE;   // BE then BO contiguous? no:
        ulonglong2* t = (ulonglong2*)Tile;
        #pragma unroll
        for (int i = 0; i < 4; i++)                      // 16KB BE
            t[tid + i * 256] = g[tid + i * 256];
        g = (const ulonglong2*)d_BO;
        #pragma unroll
        for (int i = 0; i < 4; i++)                      // 16KB BO
            t[1024 + tid + i * 256] = g[tid + i * 256];
    }
    __syncthreads();                                     // B1

    // ---- GEMM1: p rows {2l,2l+1,126-2l,127-2l}, jh cols {4w..4w+3} ----
    u64v aTe[4][4], aTo[4][4];
    #pragma unroll
    for (int pp = 0; pp < 4; pp++)
        #pragma unroll
        for (int jj = 0; jj < 4; jj++) { aTe[pp][jj] = 0ull; aTo[pp][jj] = 0ull; }

    const float2* BEt = Tile;            // [64][32]
    const float2* BOt = Tile + 64 * 32;

    #pragma unroll 8
    for (int k = 0; k < 64; k++) {
        const float* xeR = Xe + k * XE_ROW;
        const float* xoR = Xo + k * XE_ROW;
        float2 xe01 = *(const float2*)&xeR[2 * l];
        float2 xe23 = *(const float2*)&xeR[126 - 2 * l];
        float2 xo01 = *(const float2*)&xoR[2 * l];
        float2 xo23 = *(const float2*)&xoR[126 - 2 * l];
        const ulonglong2* bep = (const ulonglong2*)&BEt[k * 32 + 4 * w];
        ulonglong2 beA = bep[0], beB = bep[1];
        const ulonglong2* bop = (const ulonglong2*)&BOt[k * 32 + 4 * w];
        ulonglong2 boA = bop[0], boB = bop[1];
        u64v be[4] = {beA.x, beA.y, beB.x, beB.y};
        u64v bo[4] = {boA.x, boA.y, boB.x, boB.y};
        float xes[4] = {xe01.x, xe01.y, xe23.x, xe23.y};  // p=2l,2l+1,126-2l,127-2l
        float xos[4] = {xo01.x, xo01.y, xo23.x, xo23.y};
        #pragma unroll
        for (int pp = 0; pp < 4; pp++) {
            u64v xsE = pk2(xes[pp], xes[pp]);
            u64v xsO = pk2(xos[pp], xos[pp]);
            #pragma unroll
            for (int jj = 0; jj < 4; jj++) {
                ffma2(aTe[pp][jj], xsE, be[jj]);
                ffma2(aTo[pp][jj], xsO, bo[jj]);
            }
        }
    }

    __syncthreads();                                     // B2: GEMM1 reads done

    // ---- stage ASE+ASO tiles (overwrites BE/BO) ----
    {
        const ulonglong2* g = (const ulonglong2*)d_ASE;
        ulonglong2* t = (ulonglong2*)Tile;
        #pragma unroll
        for (int i = 0; i < 4; i++)
            t[tid + i * 256] = g[tid + i * 256];
        g = (const ulonglong2*)d_ASO;
        #pragma unroll
        for (int i = 0; i < 4; i++)
            t[1024 + tid + i * 256] = g[tid + i * 256];
    }

    // ---- fold T in p (thread-local mirror pairs), write Tpe/Tpo ----
    // pairs: (pp0=2l, pp3=127-2l) -> row 2l ; (pp1=2l+1, pp2=126-2l) -> row 2l+1
    float2* Tpe = (float2*)smem;                 // [64][66]
    float2* Tpo = (float2*)(smem + 64 * XE_ROW); // [64][66]
    #pragma unroll
    for (int r = 0; r < 2; r++) {
        int ppA = r ? 1 : 0;
        int ppB = r ? 2 : 3;
        int prow = 2 * l + r;
        #pragma unroll
        for (int jj = 0; jj < 4; jj++) {
            int jh = 4 * w + jj;
            float eAr, eAi, oAr, oAi, eBr, eBi, oBr, oBi;
            upk2(eAr, eAi, aTe[ppA][jj]);
            upk2(oAr, oAi, aTo[ppA][jj]);
            upk2(eBr, eBi, aTe[ppB][jj]);
            upk2(oBr, oBi, aTo[ppB][jj]);
            // T[ppA][jh], T[ppA][63-jh], T[ppB][jh], T[ppB][63-jh]
            float TjAr = eAr + oAr, TjAi = eAi + oAi;
            float TmAr = eAr - oAr, TmAi = eAi - oAi;
            float TjBr = eBr + oBr, TjBi = eBi + oBi;
            float TmBr = eBr - oBr, TmBi = eBi - oBi;
            Tpe[prow * TS_ROW + jh]        = make_float2(TjAr + TjBr, TjAi + TjBi);
            Tpo[prow * TS_ROW + jh]        = make_float2(TjAr - TjBr, TjAi - TjBi);
            Tpe[prow * TS_ROW + (63 - jh)] = make_float2(TmAr + TmBr, TmAi + TmBi);
            Tpo[prow * TS_ROW + (63 - jh)] = make_float2(TmAr - TmBr, TmAi - TmBi);
        }
    }
    __syncthreads();                                     // B3: Tpe/Tpo + tiles ready

    // ---- GEMM2: i = l (<32), j cols 8w..8w+7 ----
    u64v accAe[8], accBe[8], accAo[8], accBo[8];
    #pragma unroll
    for (int jj = 0; jj < 8; jj++) {
        accAe[jj] = 0ull; accBe[jj] = 0ull; accAo[jj] = 0ull; accBo[jj] = 0ull;
    }

    const float2* ASEt = Tile;            // [64][32]
    const float2* ASOt = Tile + 64 * 32;

    #pragma unroll 4
    for (int p = 0; p < 64; p++) {
        float2 ase = ASEt[p * 32 + l];
        float2 aso = ASOt[p * 32 + l];
        const ulonglong2* tep = (const ulonglong2*)&Tpe[p * TS_ROW + 8 * w];
        ulonglong2 te0 = tep[0], te1 = tep[1], te2 = tep[2], te3 = tep[3];
        u64v te[8] = {te0.x, te0.y, te1.x, te1.y, te2.x, te2.y, te3.x, te3.y};
        u64v axe = pk2(ase.x, ase.x), aye = pk2(ase.y, ase.y);
        #pragma unroll
        for (int jj = 0; jj < 8; jj++) {
            ffma2(accAe[jj], axe, te[jj]);
            ffma2(accBe[jj], aye, te[jj]);
        }
        const ulonglong2* top = (const ulonglong2*)&Tpo[p * TS_ROW + 8 * w];
        ulonglong2 to0 = top[0], to1 = top[1], to2 = top[2], to3 = top[3];
        u64v to[8] = {to0.x, to0.y, to1.x, to1.y, to2.x, to2.y, to3.x, to3.y};
        u64v axo = pk2(aso.x, aso.x), ayo = pk2(aso.y, aso.y);
        #pragma unroll
        for (int jj = 0; jj < 8; jj++) {
            ffma2(accAo[jj], axo, to[jj]);
            ffma2(accBo[jj], ayo, to[jj]);
        }
    }

    // ---- epilogue: O[l][j] = Oe+Oo, O[63-l][j] = Oe-Oo ----
    float* og = out + (size_t)img * (NSMALL * NSMALL);
    float r0[8], r1[8];
    #pragma unroll
    for (int jj = 0; jj < 8; jj++) {
        float Aer, Aei, Ber, Bei, Aor, Aoi, Bor, Boi;
        upk2(Aer, Aei, accAe[jj]);
        upk2(Ber, Bei, accBe[jj]);
        upk2(Aor, Aoi, accAo[jj]);
        upk2(Bor, Boi, accBo[jj]);
        float Oer = Aer - Bei, Oei = Aei + Ber;
        float Oor = Aor - Boi, Ooi = Aoi + Bor;
        float ar = Oer + Oor, ai = Oei + Ooi;       // row l
        float br = Oer - Oor, bi = Oei - Ooi;       // row 63-l
        r0[jj] = sqrtf(ar * ar + ai * ai);
        r1[jj] = sqrtf(br * br + bi * bi);
    }
    *(float4*)&og[l * NSMALL + 8 * w]            = make_float4(r0[0], r0[1], r0[2], r0[3]);
    *(float4*)&og[l * NSMALL + 8 * w + 4]        = make_float4(r0[4], r0[5], r0[6], r0[7]);
    *(float4*)&og[(63 - l) * NSMALL + 8 * w]     = make_float4(r1[0], r1[1], r1[2], r1[3]);
    *(float4*)&og[(63 - l) * NSMALL + 8 * w + 4] = make_float4(r1[4], r1[5], r1[6], r1[7]);
}

// ---------------------------------------------------------------------
extern "C" void kernel_launch(void* const* d_in, const int* in_sizes, int n_in,
                              void* d_out, int out_size) {
    const float* x  = (const float*)d_in[0];
    const float* o1 = (const float*)d_in[1];
    const float* o2 = (const float*)d_in[2];
    float* out = (float*)d_out;

    build_tables<<<dim3(4, 8), 128>>>(o1, o2);
    build_matrix<<<dim3(NBIG, 4), 128>>>();
    combine<<<dim3(32, 2), 128>>>();

    cudaFuncSetAttribute(frft_pool_main,
                         cudaFuncAttributeMaxDynamicSharedMemorySize, SMEM_BYTES);
    frft_pool_main<<<NIMG, 256, SMEM_BYTES>>>(x, out);
}